// round 13
// baseline (speedup 1.0000x reference)
#include <cuda_runtime.h>
#include <cuda_fp16.h>
#include <cstdint>

#define MM 8192
#define KK 4096
#define NN 4096

// GEMM tiling (fp16 mainloop)
#define BM 256
#define BN 128
#define BK 64             // K elems per stage (128 bytes of fp16)
#define NST 4
#define NCHUNK (KK / BK)  // 64
#define RS 144            // smem row stride bytes (128B data + 16B pad)

#define A_STG (BM * RS)           // 36864
#define B_STG (BN * RS)           // 18432
#define STG (A_STG + B_STG)       // 55296
#define SMEM_REQ (NST * STG)      // 221184

#define PMAX_BLOCKS 128           // 4 n-groups x 32 k-chunks

// Scratch (device globals — no allocation allowed)
__device__ __half g_qA[(size_t)MM * KK];   // [M][K] fp16 (integer values)
__device__ __half g_qBT[(size_t)NN * KK];  // [N][K] fp16 (B transposed)
__device__ float g_lsc[MM];
__device__ float g_rsc[NN];
__device__ float g_pmax[32 * NN];

__device__ __forceinline__ float qclip(float v, float s) {
    return fminf(fmaxf(rintf(v / s), -127.0f), 127.0f);
}

// ---------------------------------------------------------------------------
// Kernel 1 (fused): lhs row-quant + rhs column pmax (concurrent streams).
// pmax reads WITHOUT __ldcs so rhs warms L2 for quant_rhs's second read.
// ---------------------------------------------------------------------------
__global__ __launch_bounds__(256) void fused_lhsq_pmax_kernel(
        const float* __restrict__ lhs, const float* __restrict__ rhs) {
    int t = threadIdx.x;
    if (blockIdx.x < PMAX_BLOCKS) {
        int id = blockIdx.x;
        int bx = id & 3, by = id >> 2;
        int n4 = bx * 256 + t;
        int k0 = by * 128;
        const float4* p = (const float4*)rhs + (size_t)k0 * (NN / 4) + n4;
        float4 m = make_float4(0.f, 0.f, 0.f, 0.f);
#pragma unroll 8
        for (int k = 0; k < 128; k++) {
            float4 v = p[(size_t)k * (NN / 4)];
            m.x = fmaxf(m.x, fabsf(v.x));
            m.y = fmaxf(m.y, fabsf(v.y));
            m.z = fmaxf(m.z, fabsf(v.z));
            m.w = fmaxf(m.w, fabsf(v.w));
        }
        ((float4*)g_pmax)[by * (NN / 4) + n4] = m;
        return;
    }
    int row = blockIdx.x - PMAX_BLOCKS;
    const float4* src = (const float4*)(lhs + (size_t)row * KK);
    float4 v[4];
    v[0] = __ldcs(src + 2 * t);
    v[1] = __ldcs(src + 2 * t + 1);
    v[2] = __ldcs(src + 512 + 2 * t);
    v[3] = __ldcs(src + 512 + 2 * t + 1);
    float m = 0.0f;
#pragma unroll
    for (int i = 0; i < 4; i++)
        m = fmaxf(m, fmaxf(fmaxf(fabsf(v[i].x), fabsf(v[i].y)),
                           fmaxf(fabsf(v[i].z), fabsf(v[i].w))));
#pragma unroll
    for (int o = 16; o > 0; o >>= 1) m = fmaxf(m, __shfl_xor_sync(0xffffffffu, m, o));
    __shared__ float red[8];
    if ((t & 31) == 0) red[t >> 5] = m;
    __syncthreads();
    m = red[0];
#pragma unroll
    for (int i = 1; i < 8; i++) m = fmaxf(m, red[i]);

    float scale = m / 127.0f;
    if (scale == 0.0f) scale = 1.0f;
    if (t == 0) g_lsc[row] = scale;

    uint4* qdst = (uint4*)(g_qA + (size_t)row * KK);
#pragma unroll
    for (int g = 0; g < 2; g++) {
        float4 a = v[2 * g], b = v[2 * g + 1];
        __half2 h0 = __floats2half2_rn(qclip(a.x, scale), qclip(a.y, scale));
        __half2 h1 = __floats2half2_rn(qclip(a.z, scale), qclip(a.w, scale));
        __half2 h2 = __floats2half2_rn(qclip(b.x, scale), qclip(b.y, scale));
        __half2 h3 = __floats2half2_rn(qclip(b.z, scale), qclip(b.w, scale));
        uint4 u;
        u.x = *(uint32_t*)&h0; u.y = *(uint32_t*)&h1;
        u.z = *(uint32_t*)&h2; u.w = *(uint32_t*)&h3;
        qdst[g * 256 + t] = u;
    }
}

// ---------------------------------------------------------------------------
// Kernel 2: reduce pmax chunks -> per-column scales
// ---------------------------------------------------------------------------
__global__ __launch_bounds__(256) void rhs_scale_kernel() {
    int n4 = blockIdx.x * 256 + threadIdx.x;
    float4 m = make_float4(0.f, 0.f, 0.f, 0.f);
#pragma unroll
    for (int i = 0; i < 32; i++) {
        float4 v = ((const float4*)g_pmax)[i * (NN / 4) + n4];
        m.x = fmaxf(m.x, v.x); m.y = fmaxf(m.y, v.y);
        m.z = fmaxf(m.z, v.z); m.w = fmaxf(m.w, v.w);
    }
    float4 s;
    s.x = m.x / 127.0f; if (s.x == 0.0f) s.x = 1.0f;
    s.y = m.y / 127.0f; if (s.y == 0.0f) s.y = 1.0f;
    s.z = m.z / 127.0f; if (s.z == 0.0f) s.z = 1.0f;
    s.w = m.w / 127.0f; if (s.w == 0.0f) s.w = 1.0f;
    ((float4*)g_rsc)[n4] = s;
}

// ---------------------------------------------------------------------------
// Kernel 3: quantize rhs + transpose into [N][K] fp16 (last reader: __ldcs)
// ---------------------------------------------------------------------------
__global__ __launch_bounds__(256) void quant_rhs_kernel(const float* __restrict__ rhs) {
    __shared__ __half tileT[64][72];
    int k0 = blockIdx.y * 64, n0 = blockIdx.x * 64;
    int t = threadIdx.x;
    int nl4 = t & 15;
    int kl = t >> 4;
    float4 s4 = ((const float4*)g_rsc)[(n0 >> 2) + nl4];
#pragma unroll
    for (int i = 0; i < 4; i++) {
        int k = kl + i * 16;
        float4 v = __ldcs((const float4*)rhs + (size_t)(k0 + k) * (NN / 4) + (n0 >> 2) + nl4);
        tileT[nl4 * 4 + 0][k] = __float2half_rn(qclip(v.x, s4.x));
        tileT[nl4 * 4 + 1][k] = __float2half_rn(qclip(v.y, s4.y));
        tileT[nl4 * 4 + 2][k] = __float2half_rn(qclip(v.z, s4.z));
        tileT[nl4 * 4 + 3][k] = __float2half_rn(qclip(v.w, s4.w));
    }
    __syncthreads();
#pragma unroll
    for (int i = 0; i < 2; i++) {
        int idx = i * 256 + t;
        int n = idx >> 3, s8 = idx & 7;
        uint4 u = *(uint4*)&tileT[n][s8 * 8];
        *(uint4*)&g_qBT[(size_t)(n0 + n) * KK + k0 + s8 * 8] = u;
    }
}

// ---------------------------------------------------------------------------
// Kernel 4: pipelined fp16 GEMM — paired k-tiles: ONE barrier per 2 k-steps.
// Prefetch distance 2 (stages kt+2), wait_group 0 + __syncthreads per pair.
// ---------------------------------------------------------------------------
__device__ __forceinline__ void mma_f16(float& c0, float& c1, float& c2, float& c3,
                                        uint32_t a0, uint32_t a1, uint32_t a2, uint32_t a3,
                                        uint32_t b0, uint32_t b1) {
    asm volatile(
        "mma.sync.aligned.m16n8k16.row.col.f32.f16.f16.f32 "
        "{%0,%1,%2,%3}, {%4,%5,%6,%7}, {%8,%9}, {%0,%1,%2,%3};\n"
        : "+f"(c0), "+f"(c1), "+f"(c2), "+f"(c3)
        : "r"(a0), "r"(a1), "r"(a2), "r"(a3), "r"(b0), "r"(b1));
}

__device__ __forceinline__ void ldsm4(uint32_t& r0, uint32_t& r1, uint32_t& r2, uint32_t& r3,
                                      uint32_t addr) {
    asm volatile("ldmatrix.sync.aligned.m8n8.x4.shared.b16 {%0,%1,%2,%3}, [%4];"
                 : "=r"(r0), "=r"(r1), "=r"(r2), "=r"(r3) : "r"(addr));
}

__device__ __forceinline__ void cp16(uint32_t smem, const void* g) {
    asm volatile("cp.async.cg.shared.global [%0], [%1], 16;" :: "r"(smem), "l"(g));
}

__global__ void __launch_bounds__(512, 1)
gemm_f16_kernel(float* __restrict__ out) {
    extern __shared__ signed char sm[];
    uint32_t smb = (uint32_t)__cvta_generic_to_shared(sm);

    int tid = threadIdx.x;
    int warp = tid >> 5, lane = tid & 31;
    int wm = (warp & 3) * 64;
    int wn = (warp >> 2) * 32;
    int bm = blockIdx.y * BM, bn = blockIdx.x * BN;
    int grp = lane >> 2, tq = lane & 3;

    const __half* gAb = g_qA + (size_t)(bm + (tid >> 3)) * KK + (tid & 7) * 8;
    uint32_t sAb = smb + (tid >> 3) * RS + (tid & 7) * 16;
    const __half* gBb = g_qBT + (size_t)(bn + (tid >> 3)) * KK + (tid & 7) * 8;
    uint32_t sBb = smb + A_STG + (tid >> 3) * RS + (tid & 7) * 16;

    uint32_t aLd = smb + (wm + (lane & 15)) * RS + (lane >> 4) * 16;
    uint32_t bLd = smb + A_STG +
                   (wn + ((lane >> 4) & 1) * 8 + (lane & 7)) * RS + ((lane >> 3) & 1) * 16;

    float acc[4][4][4];
#pragma unroll
    for (int mi = 0; mi < 4; mi++)
#pragma unroll
        for (int ni = 0; ni < 4; ni++)
#pragma unroll
            for (int r = 0; r < 4; r++) acc[mi][ni][r] = 0.0f;

    // Prologue: stages 0 and 1 (prefetch distance 2)
#pragma unroll
    for (int st = 0; st < 2; st++) {
#pragma unroll
        for (int p = 0; p < 4; p++)
            cp16(sAb + st * STG + p * 64 * RS, gAb + st * BK + (size_t)p * 64 * KK);
#pragma unroll
        for (int p = 0; p < 2; p++)
            cp16(sBb + st * STG + p * 64 * RS, gBb + st * BK + (size_t)p * 64 * KK);
        asm volatile("cp.async.commit_group;");
    }

    for (int ktp = 0; ktp < NCHUNK / 2; ktp++) {
        int kt0 = 2 * ktp;
        asm volatile("cp.async.wait_group 0;");
        __syncthreads();   // stages kt0 and kt0+1 fully visible to all threads

#pragma unroll
        for (int half = 0; half < 2; half++) {
            int kt = kt0 + half;
            uint32_t stoff = (kt & 3) * STG;
            bool pf = (kt + 2 < NCHUNK);
            uint32_t pstoff = ((kt + 2) & 3) * STG;
            int ko = (kt + 2) * BK;

            uint32_t a[4][4], b[2][4][2];
#pragma unroll
            for (int mi = 0; mi < 4; mi++)
                ldsm4(a[mi][0], a[mi][1], a[mi][2], a[mi][3],
                      aLd + stoff + mi * 16 * RS);
#pragma unroll
            for (int np = 0; np < 2; np++)
                ldsm4(b[0][2 * np][0], b[0][2 * np][1], b[0][2 * np + 1][0], b[0][2 * np + 1][1],
                      bLd + stoff + np * 16 * RS);

#pragma unroll
            for (int ks = 0; ks < 4; ks++) {
                int cur = ks & 1;
                if (ks < 3) {
#pragma unroll
                    for (int np = 0; np < 2; np++)
                        ldsm4(b[cur ^ 1][2 * np][0], b[cur ^ 1][2 * np][1],
                              b[cur ^ 1][2 * np + 1][0], b[cur ^ 1][2 * np + 1][1],
                              bLd + stoff + np * 16 * RS + (ks + 1) * 32);
                }
                if (pf) {
                    if (ks == 0) {
                        cp16(sAb + pstoff + 0 * 64 * RS, gAb + ko + (size_t)0 * 64 * KK);
                        cp16(sAb + pstoff + 1 * 64 * RS, gAb + ko + (size_t)1 * 64 * KK);
                    } else if (ks == 1) {
                        cp16(sAb + pstoff + 2 * 64 * RS, gAb + ko + (size_t)2 * 64 * KK);
                        cp16(sAb + pstoff + 3 * 64 * RS, gAb + ko + (size_t)3 * 64 * KK);
                    } else if (ks == 2) {
                        cp16(sBb + pstoff + 0 * 64 * RS, gBb + ko + (size_t)0 * 64 * KK);
                        cp16(sBb + pstoff + 1 * 64 * RS, gBb + ko + (size_t)1 * 64 * KK);
                    }
                }
#pragma unroll
                for (int mi = 0; mi < 4; mi++) {
#pragma unroll
                    for (int ni = 0; ni < 4; ni++)
                        mma_f16(acc[mi][ni][0], acc[mi][ni][1], acc[mi][ni][2], acc[mi][ni][3],
                                a[mi][0], a[mi][1], a[mi][2], a[mi][3],
                                b[cur][ni][0], b[cur][ni][1]);
                    if (ks < 3)
                        ldsm4(a[mi][0], a[mi][1], a[mi][2], a[mi][3],
                              aLd + stoff + mi * 16 * RS + (ks + 1) * 32);
                }
            }
            asm volatile("cp.async.commit_group;");
        }
    }

    // Epilogue: dequant + store
#pragma unroll
    for (int mi = 0; mi < 4; mi++) {
        int gm0 = bm + wm + mi * 16 + grp;
        float s0 = g_lsc[gm0];
        float s1 = g_lsc[gm0 + 8];
#pragma unroll
        for (int ni = 0; ni < 4; ni++) {
            int gn = bn + wn + ni * 8 + tq * 2;
            float r0 = g_rsc[gn];
            float r1 = g_rsc[gn + 1];
            float2 o0, o1;
            o0.x = acc[mi][ni][0] * s0 * r0;
            o0.y = acc[mi][ni][1] * s0 * r1;
            o1.x = acc[mi][ni][2] * s1 * r0;
            o1.y = acc[mi][ni][3] * s1 * r1;
            *(float2*)(out + (size_t)gm0 * NN + gn) = o0;
            *(float2*)(out + (size_t)(gm0 + 8) * NN + gn) = o1;
        }
    }
}

// ---------------------------------------------------------------------------
extern "C" void kernel_launch(void* const* d_in, const int* in_sizes, int n_in,
                              void* d_out, int out_size) {
    const float* lhs = (const float*)d_in[0];
    const float* rhs = (const float*)d_in[1];
    if (n_in >= 2 && in_sizes[0] == KK * NN && in_sizes[1] == MM * KK) {
        const float* t = lhs; lhs = rhs; rhs = t;
    }
    float* out = (float*)d_out;

    cudaFuncSetAttribute(gemm_f16_kernel, cudaFuncAttributeMaxDynamicSharedMemorySize, SMEM_REQ);

    fused_lhsq_pmax_kernel<<<MM + PMAX_BLOCKS, 256>>>(lhs, rhs);
    rhs_scale_kernel<<<NN / 1024, 256>>>();
    quant_rhs_kernel<<<dim3(NN / 64, KK / 64), 256>>>(rhs);
    gemm_f16_kernel<<<dim3(NN / BN, MM / BM), 512, SMEM_REQ>>>(out);
}

// round 14
// speedup vs baseline: 1.0604x; 1.0604x over previous
#include <cuda_runtime.h>
#include <cuda_fp16.h>
#include <cstdint>

#define MM 8192
#define KK 4096
#define NN 4096

// GEMM tiling (fp16 mainloop) — R12 configuration (best GEMM: 666us)
#define BM 256
#define BN 128
#define BK 64             // K elems per stage (128 bytes of fp16)
#define NST 4
#define NCHUNK (KK / BK)  // 64
#define RS 144            // smem row stride bytes (128B data + 16B pad)

#define A_STG (BM * RS)           // 36864
#define B_STG (BN * RS)           // 18432
#define STG (A_STG + B_STG)       // 55296
#define SMEM_REQ (NST * STG)      // 221184

// Scratch (device globals — no allocation allowed)
__device__ __half g_qA[(size_t)MM * KK];   // [M][K] fp16 (integer values)
__device__ __half g_qBT[(size_t)NN * KK];  // [N][K] fp16 (B transposed)
__device__ float g_lsc[MM];
__device__ float g_rsc[NN];
__device__ float g_pmax[32 * NN];

__device__ __forceinline__ float qclip(float v, float s) {
    return fminf(fmaxf(rintf(v / s), -127.0f), 127.0f);
}

// ---------------------------------------------------------------------------
// Kernel 1: rhs column pmax (standalone -> shortest path to rhs_scale).
// No __ldcs: warms L2 so the quant_rhs re-read hits L2.
// ---------------------------------------------------------------------------
__global__ __launch_bounds__(256) void rhs_pmax_kernel(const float* __restrict__ rhs) {
    int bx = blockIdx.x & 3, by = blockIdx.x >> 2;
    int n4 = bx * 256 + threadIdx.x;
    int k0 = by * 128;
    const float4* p = (const float4*)rhs + (size_t)k0 * (NN / 4) + n4;
    float4 m = make_float4(0.f, 0.f, 0.f, 0.f);
#pragma unroll 8
    for (int k = 0; k < 128; k++) {
        float4 v = p[(size_t)k * (NN / 4)];
        m.x = fmaxf(m.x, fabsf(v.x));
        m.y = fmaxf(m.y, fabsf(v.y));
        m.z = fmaxf(m.z, fabsf(v.z));
        m.w = fmaxf(m.w, fabsf(v.w));
    }
    ((float4*)g_pmax)[by * (NN / 4) + n4] = m;
}

// ---------------------------------------------------------------------------
// Kernel 2: reduce pmax chunks -> per-column scales
// ---------------------------------------------------------------------------
__global__ __launch_bounds__(256) void rhs_scale_kernel() {
    int n4 = blockIdx.x * 256 + threadIdx.x;
    float4 m = make_float4(0.f, 0.f, 0.f, 0.f);
#pragma unroll
    for (int i = 0; i < 32; i++) {
        float4 v = ((const float4*)g_pmax)[i * (NN / 4) + n4];
        m.x = fmaxf(m.x, v.x); m.y = fmaxf(m.y, v.y);
        m.z = fmaxf(m.z, v.z); m.w = fmaxf(m.w, v.w);
    }
    float4 s;
    s.x = m.x / 127.0f; if (s.x == 0.0f) s.x = 1.0f;
    s.y = m.y / 127.0f; if (s.y == 0.0f) s.y = 1.0f;
    s.z = m.z / 127.0f; if (s.z == 0.0f) s.z = 1.0f;
    s.w = m.w / 127.0f; if (s.w == 0.0f) s.w = 1.0f;
    ((float4*)g_rsc)[n4] = s;
}

// ---------------------------------------------------------------------------
// Kernel 3 (fused): lhs row-quant AND rhs quant+transpose, interleaved 2:1
// by blockIdx so both independent streams run concurrently.
//   bx % 3 == 2 -> rhs tile (4096 blocks);  else -> lhs row (8192 blocks)
// ---------------------------------------------------------------------------
__global__ __launch_bounds__(256) void fused_quant_kernel(
        const float* __restrict__ lhs, const float* __restrict__ rhs) {
    __shared__ __half tileT[64][72];
    int t = threadIdx.x;
    int bx = blockIdx.x;

    if (bx % 3 == 2) {
        // ---- rhs quant + transpose tile ----
        int rid = bx / 3;                 // 0..4095
        int n0 = (rid & 63) * 64;
        int k0 = (rid >> 6) * 64;
        int nl4 = t & 15;
        int kl = t >> 4;
        float4 s4 = ((const float4*)g_rsc)[(n0 >> 2) + nl4];
#pragma unroll
        for (int i = 0; i < 4; i++) {
            int k = kl + i * 16;
            float4 v = __ldcs((const float4*)rhs + (size_t)(k0 + k) * (NN / 4) + (n0 >> 2) + nl4);
            tileT[nl4 * 4 + 0][k] = __float2half_rn(qclip(v.x, s4.x));
            tileT[nl4 * 4 + 1][k] = __float2half_rn(qclip(v.y, s4.y));
            tileT[nl4 * 4 + 2][k] = __float2half_rn(qclip(v.z, s4.z));
            tileT[nl4 * 4 + 3][k] = __float2half_rn(qclip(v.w, s4.w));
        }
        __syncthreads();
#pragma unroll
        for (int i = 0; i < 2; i++) {
            int idx = i * 256 + t;
            int n = idx >> 3, s8 = idx & 7;
            uint4 u = *(uint4*)&tileT[n][s8 * 8];
            *(uint4*)&g_qBT[(size_t)(n0 + n) * KK + k0 + s8 * 8] = u;
        }
        return;
    }

    // ---- lhs quant row ----
    int row = (bx / 3) * 2 + (bx % 3);    // 0..8191
    const float4* src = (const float4*)(lhs + (size_t)row * KK);
    float4 v[4];
    v[0] = __ldcs(src + 2 * t);
    v[1] = __ldcs(src + 2 * t + 1);
    v[2] = __ldcs(src + 512 + 2 * t);
    v[3] = __ldcs(src + 512 + 2 * t + 1);
    float m = 0.0f;
#pragma unroll
    for (int i = 0; i < 4; i++)
        m = fmaxf(m, fmaxf(fmaxf(fabsf(v[i].x), fabsf(v[i].y)),
                           fmaxf(fabsf(v[i].z), fabsf(v[i].w))));
#pragma unroll
    for (int o = 16; o > 0; o >>= 1) m = fmaxf(m, __shfl_xor_sync(0xffffffffu, m, o));
    __shared__ float red[8];
    if ((t & 31) == 0) red[t >> 5] = m;
    __syncthreads();
    m = red[0];
#pragma unroll
    for (int i = 1; i < 8; i++) m = fmaxf(m, red[i]);

    float scale = m / 127.0f;
    if (scale == 0.0f) scale = 1.0f;
    if (t == 0) g_lsc[row] = scale;

    uint4* qdst = (uint4*)(g_qA + (size_t)row * KK);
#pragma unroll
    for (int g = 0; g < 2; g++) {
        float4 a = v[2 * g], b = v[2 * g + 1];
        __half2 h0 = __floats2half2_rn(qclip(a.x, scale), qclip(a.y, scale));
        __half2 h1 = __floats2half2_rn(qclip(a.z, scale), qclip(a.w, scale));
        __half2 h2 = __floats2half2_rn(qclip(b.x, scale), qclip(b.y, scale));
        __half2 h3 = __floats2half2_rn(qclip(b.z, scale), qclip(b.w, scale));
        uint4 u;
        u.x = *(uint32_t*)&h0; u.y = *(uint32_t*)&h1;
        u.z = *(uint32_t*)&h2; u.w = *(uint32_t*)&h3;
        qdst[g * 256 + t] = u;
    }
}

// ---------------------------------------------------------------------------
// Kernel 4: pipelined fp16 GEMM — bit-exact R12 (best: 666us)
// ---------------------------------------------------------------------------
__device__ __forceinline__ void mma_f16(float& c0, float& c1, float& c2, float& c3,
                                        uint32_t a0, uint32_t a1, uint32_t a2, uint32_t a3,
                                        uint32_t b0, uint32_t b1) {
    asm volatile(
        "mma.sync.aligned.m16n8k16.row.col.f32.f16.f16.f32 "
        "{%0,%1,%2,%3}, {%4,%5,%6,%7}, {%8,%9}, {%0,%1,%2,%3};\n"
        : "+f"(c0), "+f"(c1), "+f"(c2), "+f"(c3)
        : "r"(a0), "r"(a1), "r"(a2), "r"(a3), "r"(b0), "r"(b1));
}

__device__ __forceinline__ void ldsm4(uint32_t& r0, uint32_t& r1, uint32_t& r2, uint32_t& r3,
                                      uint32_t addr) {
    asm volatile("ldmatrix.sync.aligned.m8n8.x4.shared.b16 {%0,%1,%2,%3}, [%4];"
                 : "=r"(r0), "=r"(r1), "=r"(r2), "=r"(r3) : "r"(addr));
}

__device__ __forceinline__ void cp16(uint32_t smem, const void* g) {
    asm volatile("cp.async.cg.shared.global [%0], [%1], 16;" :: "r"(smem), "l"(g));
}

__global__ void __launch_bounds__(512, 1)
gemm_f16_kernel(float* __restrict__ out) {
    extern __shared__ signed char sm[];
    uint32_t smb = (uint32_t)__cvta_generic_to_shared(sm);

    int tid = threadIdx.x;
    int warp = tid >> 5, lane = tid & 31;
    int wm = (warp & 3) * 64;
    int wn = (warp >> 2) * 32;
    int bm = blockIdx.y * BM, bn = blockIdx.x * BN;
    int grp = lane >> 2, tq = lane & 3;

    const __half* gAb = g_qA + (size_t)(bm + (tid >> 3)) * KK + (tid & 7) * 8;
    uint32_t sAb = smb + (tid >> 3) * RS + (tid & 7) * 16;
    const __half* gBb = g_qBT + (size_t)(bn + (tid >> 3)) * KK + (tid & 7) * 8;
    uint32_t sBb = smb + A_STG + (tid >> 3) * RS + (tid & 7) * 16;

    uint32_t aLd = smb + (wm + (lane & 15)) * RS + (lane >> 4) * 16;
    uint32_t bLd = smb + A_STG +
                   (wn + ((lane >> 4) & 1) * 8 + (lane & 7)) * RS + ((lane >> 3) & 1) * 16;

    float acc[4][4][4];
#pragma unroll
    for (int mi = 0; mi < 4; mi++)
#pragma unroll
        for (int ni = 0; ni < 4; ni++)
#pragma unroll
            for (int r = 0; r < 4; r++) acc[mi][ni][r] = 0.0f;

#pragma unroll
    for (int st = 0; st < NST - 1; st++) {
#pragma unroll
        for (int p = 0; p < 4; p++)
            cp16(sAb + st * STG + p * 64 * RS, gAb + st * BK + (size_t)p * 64 * KK);
#pragma unroll
        for (int p = 0; p < 2; p++)
            cp16(sBb + st * STG + p * 64 * RS, gBb + st * BK + (size_t)p * 64 * KK);
        asm volatile("cp.async.commit_group;");
    }

    int stage = 0;
    for (int kt = 0; kt < NCHUNK; kt++) {
        asm volatile("cp.async.wait_group %0;" :: "n"(NST - 2));
        __syncthreads();

        bool pf = (kt + NST - 1 < NCHUNK);
        int pst = (stage + NST - 1 >= NST) ? stage - 1 : stage + NST - 1;
        int ko = (kt + NST - 1) * BK;
        uint32_t stoff = stage * STG;

        uint32_t a[4][4], b[2][4][2];
#pragma unroll
        for (int mi = 0; mi < 4; mi++)
            ldsm4(a[mi][0], a[mi][1], a[mi][2], a[mi][3],
                  aLd + stoff + mi * 16 * RS);
#pragma unroll
        for (int np = 0; np < 2; np++)
            ldsm4(b[0][2 * np][0], b[0][2 * np][1], b[0][2 * np + 1][0], b[0][2 * np + 1][1],
                  bLd + stoff + np * 16 * RS);

#pragma unroll
        for (int ks = 0; ks < 4; ks++) {
            int cur = ks & 1;
            if (ks < 3) {
#pragma unroll
                for (int np = 0; np < 2; np++)
                    ldsm4(b[cur ^ 1][2 * np][0], b[cur ^ 1][2 * np][1],
                          b[cur ^ 1][2 * np + 1][0], b[cur ^ 1][2 * np + 1][1],
                          bLd + stoff + np * 16 * RS + (ks + 1) * 32);
            }
            if (pf) {
                if (ks == 0) {
                    cp16(sAb + pst * STG + 0 * 64 * RS, gAb + ko + (size_t)0 * 64 * KK);
                    cp16(sAb + pst * STG + 1 * 64 * RS, gAb + ko + (size_t)1 * 64 * KK);
                } else if (ks == 1) {
                    cp16(sAb + pst * STG + 2 * 64 * RS, gAb + ko + (size_t)2 * 64 * KK);
                    cp16(sAb + pst * STG + 3 * 64 * RS, gAb + ko + (size_t)3 * 64 * KK);
                } else if (ks == 2) {
                    cp16(sBb + pst * STG + 0 * 64 * RS, gBb + ko + (size_t)0 * 64 * KK);
                    cp16(sBb + pst * STG + 1 * 64 * RS, gBb + ko + (size_t)1 * 64 * KK);
                }
            }
#pragma unroll
            for (int mi = 0; mi < 4; mi++) {
#pragma unroll
                for (int ni = 0; ni < 4; ni++)
                    mma_f16(acc[mi][ni][0], acc[mi][ni][1], acc[mi][ni][2], acc[mi][ni][3],
                            a[mi][0], a[mi][1], a[mi][2], a[mi][3],
                            b[cur][ni][0], b[cur][ni][1]);
                if (ks < 3)
                    ldsm4(a[mi][0], a[mi][1], a[mi][2], a[mi][3],
                          aLd + stoff + mi * 16 * RS + (ks + 1) * 32);
            }
        }
        asm volatile("cp.async.commit_group;");
        stage = (stage + 1 == NST) ? 0 : stage + 1;
    }

#pragma unroll
    for (int mi = 0; mi < 4; mi++) {
        int gm0 = bm + wm + mi * 16 + grp;
        float s0 = g_lsc[gm0];
        float s1 = g_lsc[gm0 + 8];
#pragma unroll
        for (int ni = 0; ni < 4; ni++) {
            int gn = bn + wn + ni * 8 + tq * 2;
            float r0 = g_rsc[gn];
            float r1 = g_rsc[gn + 1];
            float2 o0, o1;
            o0.x = acc[mi][ni][0] * s0 * r0;
            o0.y = acc[mi][ni][1] * s0 * r1;
            o1.x = acc[mi][ni][2] * s1 * r0;
            o1.y = acc[mi][ni][3] * s1 * r1;
            *(float2*)(out + (size_t)gm0 * NN + gn) = o0;
            *(float2*)(out + (size_t)(gm0 + 8) * NN + gn) = o1;
        }
    }
}

// ---------------------------------------------------------------------------
extern "C" void kernel_launch(void* const* d_in, const int* in_sizes, int n_in,
                              void* d_out, int out_size) {
    const float* lhs = (const float*)d_in[0];
    const float* rhs = (const float*)d_in[1];
    if (n_in >= 2 && in_sizes[0] == KK * NN && in_sizes[1] == MM * KK) {
        const float* t = lhs; lhs = rhs; rhs = t;
    }
    float* out = (float*)d_out;

    cudaFuncSetAttribute(gemm_f16_kernel, cudaFuncAttributeMaxDynamicSharedMemorySize, SMEM_REQ);

    rhs_pmax_kernel<<<128, 256>>>(rhs);
    rhs_scale_kernel<<<NN / 1024, 256>>>();
    fused_quant_kernel<<<MM + NN * KK / (64 * 64), 256>>>(lhs, rhs);  // 12288 blocks
    gemm_f16_kernel<<<dim3(NN / BN, MM / BM), 512, SMEM_REQ>>>(out);
}

// round 15
// speedup vs baseline: 1.0656x; 1.0049x over previous
#include <cuda_runtime.h>
#include <cuda_fp16.h>
#include <cstdint>

#define MM 8192
#define KK 4096
#define NN 4096

// GEMM tiling (fp16 mainloop) — R12 configuration (best GEMM: 666us)
#define BM 256
#define BN 128
#define BK 64             // K elems per stage (128 bytes of fp16)
#define NST 4
#define NCHUNK (KK / BK)  // 64
#define RS 144            // smem row stride bytes (128B data + 16B pad)

#define A_STG (BM * RS)           // 36864
#define B_STG (BN * RS)           // 18432
#define STG (A_STG + B_STG)       // 55296
#define SMEM_REQ (NST * STG)      // 221184

#define PCHUNKS 128               // pmax k-chunks (32 rows each) -> 512 blocks

// Scratch (device globals — no allocation allowed)
__device__ __half g_qA[(size_t)MM * KK];   // [M][K] fp16 (integer values)
__device__ __half g_qBT[(size_t)NN * KK];  // [N][K] fp16 (B transposed)
__device__ float g_lsc[MM];
__device__ float g_rsc[NN];
__device__ float g_pmax[PCHUNKS * NN];

__device__ __forceinline__ float qclip(float v, float s) {
    return fminf(fmaxf(rintf(v / s), -127.0f), 127.0f);
}

// ---------------------------------------------------------------------------
// Kernel 1: rhs column pmax — 512 blocks (128 k-chunks x 4 n-groups) for
// full-chip parallelism. No __ldcs: warms L2 for the quant_rhs re-read.
// ---------------------------------------------------------------------------
__global__ __launch_bounds__(256) void rhs_pmax_kernel(const float* __restrict__ rhs) {
    int bx = blockIdx.x & 3, by = blockIdx.x >> 2;   // by: 0..127
    int n4 = bx * 256 + threadIdx.x;
    int k0 = by * 32;
    const float4* p = (const float4*)rhs + (size_t)k0 * (NN / 4) + n4;
    float4 m = make_float4(0.f, 0.f, 0.f, 0.f);
#pragma unroll 8
    for (int k = 0; k < 32; k++) {
        float4 v = p[(size_t)k * (NN / 4)];
        m.x = fmaxf(m.x, fabsf(v.x));
        m.y = fmaxf(m.y, fabsf(v.y));
        m.z = fmaxf(m.z, fabsf(v.z));
        m.w = fmaxf(m.w, fabsf(v.w));
    }
    ((float4*)g_pmax)[by * (NN / 4) + n4] = m;
}

// ---------------------------------------------------------------------------
// Kernel 2: reduce pmax chunks -> per-column scales
// ---------------------------------------------------------------------------
__global__ __launch_bounds__(256) void rhs_scale_kernel() {
    int n4 = blockIdx.x * 256 + threadIdx.x;
    float4 m = make_float4(0.f, 0.f, 0.f, 0.f);
#pragma unroll 8
    for (int i = 0; i < PCHUNKS; i++) {
        float4 v = ((const float4*)g_pmax)[i * (NN / 4) + n4];
        m.x = fmaxf(m.x, v.x); m.y = fmaxf(m.y, v.y);
        m.z = fmaxf(m.z, v.z); m.w = fmaxf(m.w, v.w);
    }
    float4 s;
    s.x = m.x / 127.0f; if (s.x == 0.0f) s.x = 1.0f;
    s.y = m.y / 127.0f; if (s.y == 0.0f) s.y = 1.0f;
    s.z = m.z / 127.0f; if (s.z == 0.0f) s.z = 1.0f;
    s.w = m.w / 127.0f; if (s.w == 0.0f) s.w = 1.0f;
    ((float4*)g_rsc)[n4] = s;
}

// ---------------------------------------------------------------------------
// Kernel 3 (fused): lhs row-quant AND rhs quant+transpose, interleaved 2:1
// ---------------------------------------------------------------------------
__global__ __launch_bounds__(256) void fused_quant_kernel(
        const float* __restrict__ lhs, const float* __restrict__ rhs) {
    __shared__ __half tileT[64][72];
    int t = threadIdx.x;
    int bx = blockIdx.x;

    if (bx % 3 == 2) {
        int rid = bx / 3;                 // 0..4095
        int n0 = (rid & 63) * 64;
        int k0 = (rid >> 6) * 64;
        int nl4 = t & 15;
        int kl = t >> 4;
        float4 s4 = ((const float4*)g_rsc)[(n0 >> 2) + nl4];
#pragma unroll
        for (int i = 0; i < 4; i++) {
            int k = kl + i * 16;
            float4 v = __ldcs((const float4*)rhs + (size_t)(k0 + k) * (NN / 4) + (n0 >> 2) + nl4);
            tileT[nl4 * 4 + 0][k] = __float2half_rn(qclip(v.x, s4.x));
            tileT[nl4 * 4 + 1][k] = __float2half_rn(qclip(v.y, s4.y));
            tileT[nl4 * 4 + 2][k] = __float2half_rn(qclip(v.z, s4.z));
            tileT[nl4 * 4 + 3][k] = __float2half_rn(qclip(v.w, s4.w));
        }
        __syncthreads();
#pragma unroll
        for (int i = 0; i < 2; i++) {
            int idx = i * 256 + t;
            int n = idx >> 3, s8 = idx & 7;
            uint4 u = *(uint4*)&tileT[n][s8 * 8];
            *(uint4*)&g_qBT[(size_t)(n0 + n) * KK + k0 + s8 * 8] = u;
        }
        return;
    }

    int row = (bx / 3) * 2 + (bx % 3);    // 0..8191
    const float4* src = (const float4*)(lhs + (size_t)row * KK);
    float4 v[4];
    v[0] = __ldcs(src + 2 * t);
    v[1] = __ldcs(src + 2 * t + 1);
    v[2] = __ldcs(src + 512 + 2 * t);
    v[3] = __ldcs(src + 512 + 2 * t + 1);
    float m = 0.0f;
#pragma unroll
    for (int i = 0; i < 4; i++)
        m = fmaxf(m, fmaxf(fmaxf(fabsf(v[i].x), fabsf(v[i].y)),
                           fmaxf(fabsf(v[i].z), fabsf(v[i].w))));
#pragma unroll
    for (int o = 16; o > 0; o >>= 1) m = fmaxf(m, __shfl_xor_sync(0xffffffffu, m, o));
    __shared__ float red[8];
    if ((t & 31) == 0) red[t >> 5] = m;
    __syncthreads();
    m = red[0];
#pragma unroll
    for (int i = 1; i < 8; i++) m = fmaxf(m, red[i]);

    float scale = m / 127.0f;
    if (scale == 0.0f) scale = 1.0f;
    if (t == 0) g_lsc[row] = scale;

    uint4* qdst = (uint4*)(g_qA + (size_t)row * KK);
#pragma unroll
    for (int g = 0; g < 2; g++) {
        float4 a = v[2 * g], b = v[2 * g + 1];
        __half2 h0 = __floats2half2_rn(qclip(a.x, scale), qclip(a.y, scale));
        __half2 h1 = __floats2half2_rn(qclip(a.z, scale), qclip(a.w, scale));
        __half2 h2 = __floats2half2_rn(qclip(b.x, scale), qclip(b.y, scale));
        __half2 h3 = __floats2half2_rn(qclip(b.z, scale), qclip(b.w, scale));
        uint4 u;
        u.x = *(uint32_t*)&h0; u.y = *(uint32_t*)&h1;
        u.z = *(uint32_t*)&h2; u.w = *(uint32_t*)&h3;
        qdst[g * 256 + t] = u;
    }
}

// ---------------------------------------------------------------------------
// Kernel 4: pipelined fp16 GEMM — bit-exact R12 (best: 666us)
// ---------------------------------------------------------------------------
__device__ __forceinline__ void mma_f16(float& c0, float& c1, float& c2, float& c3,
                                        uint32_t a0, uint32_t a1, uint32_t a2, uint32_t a3,
                                        uint32_t b0, uint32_t b1) {
    asm volatile(
        "mma.sync.aligned.m16n8k16.row.col.f32.f16.f16.f32 "
        "{%0,%1,%2,%3}, {%4,%5,%6,%7}, {%8,%9}, {%0,%1,%2,%3};\n"
        : "+f"(c0), "+f"(c1), "+f"(c2), "+f"(c3)
        : "r"(a0), "r"(a1), "r"(a2), "r"(a3), "r"(b0), "r"(b1));
}

__device__ __forceinline__ void ldsm4(uint32_t& r0, uint32_t& r1, uint32_t& r2, uint32_t& r3,
                                      uint32_t addr) {
    asm volatile("ldmatrix.sync.aligned.m8n8.x4.shared.b16 {%0,%1,%2,%3}, [%4];"
                 : "=r"(r0), "=r"(r1), "=r"(r2), "=r"(r3) : "r"(addr));
}

__device__ __forceinline__ void cp16(uint32_t smem, const void* g) {
    asm volatile("cp.async.cg.shared.global [%0], [%1], 16;" :: "r"(smem), "l"(g));
}

__global__ void __launch_bounds__(512, 1)
gemm_f16_kernel(float* __restrict__ out) {
    extern __shared__ signed char sm[];
    uint32_t smb = (uint32_t)__cvta_generic_to_shared(sm);

    int tid = threadIdx.x;
    int warp = tid >> 5, lane = tid & 31;
    int wm = (warp & 3) * 64;
    int wn = (warp >> 2) * 32;
    int bm = blockIdx.y * BM, bn = blockIdx.x * BN;
    int grp = lane >> 2, tq = lane & 3;

    const __half* gAb = g_qA + (size_t)(bm + (tid >> 3)) * KK + (tid & 7) * 8;
    uint32_t sAb = smb + (tid >> 3) * RS + (tid & 7) * 16;
    const __half* gBb = g_qBT + (size_t)(bn + (tid >> 3)) * KK + (tid & 7) * 8;
    uint32_t sBb = smb + A_STG + (tid >> 3) * RS + (tid & 7) * 16;

    uint32_t aLd = smb + (wm + (lane & 15)) * RS + (lane >> 4) * 16;
    uint32_t bLd = smb + A_STG +
                   (wn + ((lane >> 4) & 1) * 8 + (lane & 7)) * RS + ((lane >> 3) & 1) * 16;

    float acc[4][4][4];
#pragma unroll
    for (int mi = 0; mi < 4; mi++)
#pragma unroll
        for (int ni = 0; ni < 4; ni++)
#pragma unroll
            for (int r = 0; r < 4; r++) acc[mi][ni][r] = 0.0f;

#pragma unroll
    for (int st = 0; st < NST - 1; st++) {
#pragma unroll
        for (int p = 0; p < 4; p++)
            cp16(sAb + st * STG + p * 64 * RS, gAb + st * BK + (size_t)p * 64 * KK);
#pragma unroll
        for (int p = 0; p < 2; p++)
            cp16(sBb + st * STG + p * 64 * RS, gBb + st * BK + (size_t)p * 64 * KK);
        asm volatile("cp.async.commit_group;");
    }

    int stage = 0;
    for (int kt = 0; kt < NCHUNK; kt++) {
        asm volatile("cp.async.wait_group %0;" :: "n"(NST - 2));
        __syncthreads();

        bool pf = (kt + NST - 1 < NCHUNK);
        int pst = (stage + NST - 1 >= NST) ? stage - 1 : stage + NST - 1;
        int ko = (kt + NST - 1) * BK;
        uint32_t stoff = stage * STG;

        uint32_t a[4][4], b[2][4][2];
#pragma unroll
        for (int mi = 0; mi < 4; mi++)
            ldsm4(a[mi][0], a[mi][1], a[mi][2], a[mi][3],
                  aLd + stoff + mi * 16 * RS);
#pragma unroll
        for (int np = 0; np < 2; np++)
            ldsm4(b[0][2 * np][0], b[0][2 * np][1], b[0][2 * np + 1][0], b[0][2 * np + 1][1],
                  bLd + stoff + np * 16 * RS);

#pragma unroll
        for (int ks = 0; ks < 4; ks++) {
            int cur = ks & 1;
            if (ks < 3) {
#pragma unroll
                for (int np = 0; np < 2; np++)
                    ldsm4(b[cur ^ 1][2 * np][0], b[cur ^ 1][2 * np][1],
                          b[cur ^ 1][2 * np + 1][0], b[cur ^ 1][2 * np + 1][1],
                          bLd + stoff + np * 16 * RS + (ks + 1) * 32);
            }
            if (pf) {
                if (ks == 0) {
                    cp16(sAb + pst * STG + 0 * 64 * RS, gAb + ko + (size_t)0 * 64 * KK);
                    cp16(sAb + pst * STG + 1 * 64 * RS, gAb + ko + (size_t)1 * 64 * KK);
                } else if (ks == 1) {
                    cp16(sAb + pst * STG + 2 * 64 * RS, gAb + ko + (size_t)2 * 64 * KK);
                    cp16(sAb + pst * STG + 3 * 64 * RS, gAb + ko + (size_t)3 * 64 * KK);
                } else if (ks == 2) {
                    cp16(sBb + pst * STG + 0 * 64 * RS, gBb + ko + (size_t)0 * 64 * KK);
                    cp16(sBb + pst * STG + 1 * 64 * RS, gBb + ko + (size_t)1 * 64 * KK);
                }
            }
#pragma unroll
            for (int mi = 0; mi < 4; mi++) {
#pragma unroll
                for (int ni = 0; ni < 4; ni++)
                    mma_f16(acc[mi][ni][0], acc[mi][ni][1], acc[mi][ni][2], acc[mi][ni][3],
                            a[mi][0], a[mi][1], a[mi][2], a[mi][3],
                            b[cur][ni][0], b[cur][ni][1]);
                if (ks < 3)
                    ldsm4(a[mi][0], a[mi][1], a[mi][2], a[mi][3],
                          aLd + stoff + mi * 16 * RS + (ks + 1) * 32);
            }
        }
        asm volatile("cp.async.commit_group;");
        stage = (stage + 1 == NST) ? 0 : stage + 1;
    }

#pragma unroll
    for (int mi = 0; mi < 4; mi++) {
        int gm0 = bm + wm + mi * 16 + grp;
        float s0 = g_lsc[gm0];
        float s1 = g_lsc[gm0 + 8];
#pragma unroll
        for (int ni = 0; ni < 4; ni++) {
            int gn = bn + wn + ni * 8 + tq * 2;
            float r0 = g_rsc[gn];
            float r1 = g_rsc[gn + 1];
            float2 o0, o1;
            o0.x = acc[mi][ni][0] * s0 * r0;
            o0.y = acc[mi][ni][1] * s0 * r1;
            o1.x = acc[mi][ni][2] * s1 * r0;
            o1.y = acc[mi][ni][3] * s1 * r1;
            *(float2*)(out + (size_t)gm0 * NN + gn) = o0;
            *(float2*)(out + (size_t)(gm0 + 8) * NN + gn) = o1;
        }
    }
}

// ---------------------------------------------------------------------------
extern "C" void kernel_launch(void* const* d_in, const int* in_sizes, int n_in,
                              void* d_out, int out_size) {
    const float* lhs = (const float*)d_in[0];
    const float* rhs = (const float*)d_in[1];
    if (n_in >= 2 && in_sizes[0] == KK * NN && in_sizes[1] == MM * KK) {
        const float* t = lhs; lhs = rhs; rhs = t;
    }
    float* out = (float*)d_out;

    cudaFuncSetAttribute(gemm_f16_kernel, cudaFuncAttributeMaxDynamicSharedMemorySize, SMEM_REQ);

    rhs_pmax_kernel<<<PCHUNKS * 4, 256>>>(rhs);
    rhs_scale_kernel<<<NN / 1024, 256>>>();
    fused_quant_kernel<<<MM + NN * KK / (64 * 64), 256>>>(lhs, rhs);  // 12288 blocks
    gemm_f16_kernel<<<dim3(NN / BN, MM / BM), 512, SMEM_REQ>>>(out);
}